// round 2
// baseline (speedup 1.0000x reference)
#include <cuda_runtime.h>
#include <cuda_bf16.h>
#include <cstdint>

// ============================================================
// BinarizeConv2d: out = conv3x3(sign(x), sign(mix(W))) * scale * alpha
// Implicit GEMM on mma.sync m16n8k16 bf16 (exact for ±1 inputs).
// Target is plain sm_100 (no tcgen05 — harness PTX target lacks 'a').
//   M-tile = 128 rows (2 h-rows x 56 w -> 112 valid), N-tile = 128 (half C_out)
//   K = 2304 = 9 taps x 4 chunks of 64 input channels
// 4-stage cp.async pipeline, ldmatrix-fed HMMA, SMEM-staged epilogue.
// ============================================================

#define B_   32
#define CIN  256
#define COUT 256
#define H_   56
#define W_   56
#define HP   58
#define WP   58

// Device-global scratch (allocation-free). g_xb borders stay zero (static init);
// only the interior is rewritten each call => deterministic padding.
__device__ __nv_bfloat16 g_xb[(size_t)B_ * HP * WP * CIN];  // sign(x), NHWC padded
__device__ __nv_bfloat16 g_wb[9 * COUT * CIN];              // sign(real_w) [tap][co][ci]
__device__ float         g_sa[COUT];                        // alpha * scale

// ---------------- PTX helpers (all plain sm_80-era) ----------------
__device__ __forceinline__ uint32_t smem_u32(const void* p) {
    uint32_t a;
    asm("{ .reg .u64 t; cvta.to.shared.u64 t, %1; cvt.u32.u64 %0, t; }" : "=r"(a) : "l"(p));
    return a;
}
#define CP16(d, s)   asm volatile("cp.async.cg.shared.global [%0], [%1], 16;" :: "r"(d), "l"(s) : "memory")
#define CP_COMMIT()  asm volatile("cp.async.commit_group;" ::: "memory")
#define CP_WAIT(n)   asm volatile("cp.async.wait_group %0;" :: "n"(n) : "memory")

#define LDSM4(r, a)                                                          \
    asm volatile("ldmatrix.sync.aligned.m8n8.x4.shared.b16 {%0,%1,%2,%3}, [%4];" \
        : "=r"((r)[0]), "=r"((r)[1]), "=r"((r)[2]), "=r"((r)[3]) : "r"(a))

#define MMA16816(d, a, b0, b1)                                               \
    asm volatile("mma.sync.aligned.m16n8k16.row.col.f32.bf16.bf16.f32 "      \
        "{%0,%1,%2,%3}, {%4,%5,%6,%7}, {%8,%9}, {%0,%1,%2,%3};"              \
        : "+f"((d)[0]), "+f"((d)[1]), "+f"((d)[2]), "+f"((d)[3])             \
        : "r"((a)[0]), "r"((a)[1]), "r"((a)[2]), "r"((a)[3]),                \
          "r"(b0), "r"(b1))

// ---------------- prep kernel 1: weights ----------------
__global__ void prep_w(const float* __restrict__ Wt, const float* __restrict__ RV,
                       const float* __restrict__ alpha) {
    const int co = blockIdx.x, ci = threadIdx.x;
    const float r0 = RV[0], r1 = RV[1], r2 = RV[2], r3 = RV[3];
    const size_t ks = (size_t)COUT * CIN * 9;
    const float* w0 = Wt + ((size_t)co * CIN + ci) * 9;
    float acc = 0.f;
#pragma unroll
    for (int t = 0; t < 9; t++) {
        float rw = r0 * w0[t] + r1 * w0[t + ks] + r2 * w0[t + 2 * ks] + r3 * w0[t + 3 * ks];
        acc += fabsf(rw);
        float s = (rw > 0.f) ? 1.f : ((rw < 0.f) ? -1.f : 0.f);
        g_wb[((size_t)t * COUT + co) * CIN + ci] = __float2bfloat16(s);
    }
    __shared__ float red[256];
    red[ci] = acc;
    __syncthreads();
    for (int st = 128; st > 0; st >>= 1) {
        if (ci < st) red[ci] += red[ci + st];
        __syncthreads();
    }
    if (ci == 0) g_sa[co] = alpha[co] * (red[0] * (1.0f / 2304.0f));
}

// ---------------- prep kernel 2: binarize x, NCHW -> padded NHWC ----------------
__global__ void prep_x(const float* __restrict__ x) {
    const int cc = blockIdx.x;  // channel chunk (64 ch)
    const int h  = blockIdx.y;
    const int b  = blockIdx.z;
    const int tid = threadIdx.x;  // 256
    __shared__ __nv_bfloat16 sb[64 * 56];  // [ci][w]
    const float* xp = x + (((size_t)b * CIN + cc * 64) * H_ + h) * W_;
    for (int i = tid; i < 64 * 56; i += 256) {
        int ci = i / 56, w = i - ci * 56;
        float v = xp[(size_t)ci * (H_ * W_) + w];
        float s = (v > 0.f) ? 1.f : ((v < 0.f) ? -1.f : 0.f);
        sb[ci * 56 + w] = __float2bfloat16(s);
    }
    __syncthreads();
    __nv_bfloat16* dst0 = g_xb + (((size_t)b * HP + (h + 1)) * WP + 1) * CIN + cc * 64;
    for (int u = tid; u < 56 * 8; u += 256) {
        int w = u >> 3, s8 = (u & 7) * 8;
        uint32_t v4[4];
#pragma unroll
        for (int jp = 0; jp < 4; jp++) {
            __nv_bfloat16 lo = sb[(s8 + 2 * jp) * 56 + w];
            __nv_bfloat16 hi = sb[(s8 + 2 * jp + 1) * 56 + w];
            unsigned short rl = *reinterpret_cast<unsigned short*>(&lo);
            unsigned short rh = *reinterpret_cast<unsigned short*>(&hi);
            v4[jp] = (uint32_t)rl | ((uint32_t)rh << 16);
        }
        *reinterpret_cast<uint4*>(dst0 + (size_t)w * CIN + s8) =
            make_uint4(v4[0], v4[1], v4[2], v4[3]);
    }
}

// ---------------- main GEMM kernel ----------------
#define NSTG     4
#define A_BYTES  16384                 // 128 rows x 128B (rows 112..127 unused garbage)
#define STG      32768                 // A + B per stage
#define GSMEM    (NSTG * STG)          // 131072 B
#define NCHUNK   36                    // 9 taps x 4 ci-chunks of 64

__global__ void __launch_bounds__(256, 1) bconv_gemm(float* __restrict__ out) {
    extern __shared__ char smem[];
    const uint32_t sbase = smem_u32(smem);
    const int tid  = threadIdx.x;
    const int warp = tid >> 5, lane = tid & 31;
    const int mw = warp >> 1;          // 0..3: M rows 32*mw..+31
    const int nw = warp & 1;           // 0..1: N cols 64*nw..+63 (within 128-half)
    const int bidx  = blockIdx.x;
    const int co0   = (bidx & 1) * 128;
    const int mtile = bidx >> 1;
    const int b  = mtile / 28;
    const int h0 = (mtile - b * 28) * 2;

    const int seg = tid & 7;   // 16B segment within 128B k-row
    const int rb  = tid >> 3;  // base row 0..31

    // per-lane ldmatrix constants
    const int rlo   = lane & 15;
    const int khalf = (lane >> 4) << 4;        // 0 or 16 bytes
    const int swz   = (rlo & 7) << 4;

    float d[2][8][4];
#pragma unroll
    for (int mi = 0; mi < 2; mi++)
#pragma unroll
        for (int ni = 0; ni < 8; ni++)
#pragma unroll
            for (int j = 0; j < 4; j++) d[mi][ni][j] = 0.f;

    auto load_chunk = [&](int chunk, int stage) {
        const int t  = chunk >> 2;                 // tap 0..8
        const int cc = (chunk & 3) << 6;           // ci chunk base
        const int kh = t / 3, kw = t - kh * 3;
        const uint32_t stgA = sbase + stage * STG;
        const uint32_t stgB = stgA + A_BYTES;
        const __nv_bfloat16* abase =
            g_xb + (((size_t)b * HP + (h0 + kh)) * WP + kw) * CIN + cc;
#pragma unroll
        for (int k = 0; k < 4; k++) {
            int r  = rb + 32 * k;
            int rc = (r < 112) ? r : 111;          // clamp: rows 112-127 dummy
            int ha = (rc >= 56) ? 1 : 0;
            int w  = rc - 56 * ha;
            const char* src = (const char*)(abase + ((size_t)ha * WP + w) * CIN) + seg * 16;
            CP16(stgA + r * 128 + ((seg * 16) ^ ((r & 7) << 4)), src);
        }
        const char* bsrc = (const char*)(g_wb + ((size_t)t * COUT + co0) * CIN + cc);
#pragma unroll
        for (int k = 0; k < 4; k++) {
            int r = rb + 32 * k;
            const char* src = bsrc + (size_t)r * (CIN * 2) + seg * 16;
            CP16(stgB + r * 128 + ((seg * 16) ^ ((r & 7) << 4)), src);
        }
    };

    load_chunk(0, 0); CP_COMMIT();
    load_chunk(1, 1); CP_COMMIT();
    load_chunk(2, 2); CP_COMMIT();

    const int rowA0 = 32 * mw + rlo;
    const int rowB0 = 64 * nw + rlo;

    for (int i = 0; i < NCHUNK; i++) {
        CP_WAIT(2);
        __syncthreads();
        if (i + 3 < NCHUNK) load_chunk(i + 3, (i + 3) & 3);
        CP_COMMIT();

        const uint32_t stgA = sbase + (i & 3) * STG;
        const uint32_t stgB = stgA + A_BYTES;
#pragma unroll
        for (int ks = 0; ks < 4; ks++) {
            const int kb = ks * 32 + khalf;
            uint32_t a[2][4];
            LDSM4(a[0], stgA + rowA0 * 128 + (kb ^ swz));
            LDSM4(a[1], stgA + (rowA0 + 16) * 128 + (kb ^ swz));
#pragma unroll
            for (int np = 0; np < 4; np++) {
                uint32_t bf[4];
                LDSM4(bf, stgB + (rowB0 + 16 * np) * 128 + (kb ^ swz));
                MMA16816(d[0][2 * np],     a[0], bf[0], bf[2]);
                MMA16816(d[0][2 * np + 1], a[0], bf[1], bf[3]);
                MMA16816(d[1][2 * np],     a[1], bf[0], bf[2]);
                MMA16816(d[1][2 * np + 1], a[1], bf[1], bf[3]);
            }
        }
    }

    CP_WAIT(0);
    __syncthreads();

    // ---------------- epilogue: stage through SMEM, coalesced stores ----------------
    float* buf = (float*)smem;                 // 64 cl x 128 rows = 32KB (stage 0)
    const int q  = lane & 3;
    const int rr = lane >> 2;
#pragma unroll 1
    for (int hh = 0; hh < 2; hh++) {
        if (nw == hh) {
#pragma unroll
            for (int mi = 0; mi < 2; mi++)
#pragma unroll
                for (int ni = 0; ni < 8; ni++) {
                    int cl  = 8 * ni + 2 * q;
                    int row = 32 * mw + 16 * mi + rr;
                    buf[cl * 128 + row]           = d[mi][ni][0];
                    buf[(cl + 1) * 128 + row]     = d[mi][ni][1];
                    buf[cl * 128 + row + 8]       = d[mi][ni][2];
                    buf[(cl + 1) * 128 + row + 8] = d[mi][ni][3];
                }
        }
        __syncthreads();
        for (int it = 0; it < 28; it++) {
            int u  = tid + 256 * it;           // 0..7167
            int cl = u / 112;
            int r  = u - cl * 112;
            int ha = (r >= 56) ? 1 : 0;
            int w  = r - 56 * ha;
            int co = co0 + hh * 64 + cl;
            float sa = g_sa[co];
            out[(((size_t)b * COUT + co) * H_ + (h0 + ha)) * W_ + w] =
                buf[cl * 128 + r] * sa;
        }
        __syncthreads();
    }
}

// ---------------- launch ----------------
extern "C" void kernel_launch(void* const* d_in, const int* in_sizes, int n_in,
                              void* d_out, int out_size) {
    const float* x     = (const float*)d_in[0];  // [32,256,56,56]
    const float* wts   = (const float*)d_in[1];  // [4,256,256,3,3]
    const float* rv    = (const float*)d_in[2];  // [5]
    const float* alpha = (const float*)d_in[3];  // [256]
    float* out = (float*)d_out;

    cudaFuncSetAttribute(bconv_gemm, cudaFuncAttributeMaxDynamicSharedMemorySize, GSMEM);

    prep_w<<<COUT, 256>>>(wts, rv, alpha);
    prep_x<<<dim3(4, H_, B_), 256>>>(x);
    bconv_gemm<<<B_ * (H_ / 2) * 2, 256, GSMEM>>>(out);
}

// round 3
// speedup vs baseline: 1.1584x; 1.1584x over previous
#include <cuda_runtime.h>
#include <cuda_bf16.h>
#include <cstdint>

// ============================================================
// BinarizeConv2d: out = conv3x3(sign(x), sign(mix(W))) * scale * alpha
// Implicit GEMM on mma.sync m16n8k16 bf16 (exact for ±1 inputs), sm_100.
//   M-tile 128 (2 h-rows x 56 w, 112 valid), N-tile 128, K = 2304
// R3: 2 CTAs/SM (3-stage x 32KB pipeline), batched LDSM, merged prep.
// ============================================================

#define B_   32
#define CIN  256
#define COUT 256
#define H_   56
#define W_   56
#define HP   58
#define WP   58

__device__ __nv_bfloat16 g_xb[(size_t)B_ * HP * WP * CIN];  // sign(x), NHWC padded
__device__ __nv_bfloat16 g_wb[9 * COUT * CIN];              // sign(real_w) [tap][co][ci]
__device__ float         g_sa[COUT];                        // alpha * scale

// ---------------- PTX helpers ----------------
__device__ __forceinline__ uint32_t smem_u32(const void* p) {
    uint32_t a;
    asm("{ .reg .u64 t; cvta.to.shared.u64 t, %1; cvt.u32.u64 %0, t; }" : "=r"(a) : "l"(p));
    return a;
}
#define CP16(d, s)   asm volatile("cp.async.cg.shared.global [%0], [%1], 16;" :: "r"(d), "l"(s) : "memory")
#define CP_COMMIT()  asm volatile("cp.async.commit_group;" ::: "memory")
#define CP_WAIT(n)   asm volatile("cp.async.wait_group %0;" :: "n"(n) : "memory")

#define LDSM4(r, a)                                                          \
    asm volatile("ldmatrix.sync.aligned.m8n8.x4.shared.b16 {%0,%1,%2,%3}, [%4];" \
        : "=r"((r)[0]), "=r"((r)[1]), "=r"((r)[2]), "=r"((r)[3]) : "r"(a))

#define MMA16816(d, a, b0, b1)                                               \
    asm volatile("mma.sync.aligned.m16n8k16.row.col.f32.bf16.bf16.f32 "      \
        "{%0,%1,%2,%3}, {%4,%5,%6,%7}, {%8,%9}, {%0,%1,%2,%3};"              \
        : "+f"((d)[0]), "+f"((d)[1]), "+f"((d)[2]), "+f"((d)[3])             \
        : "r"((a)[0]), "r"((a)[1]), "r"((a)[2]), "r"((a)[3]),                \
          "r"(b0), "r"(b1))

// ---------------- merged prep kernel ----------------
// blocks [0,256):           weight mix/sign/scale  (co = blockIdx.x)
// blocks [256, 256+7168):   binarize x, NCHW -> padded NHWC
__global__ void prep_all(const float* __restrict__ Wt, const float* __restrict__ RV,
                         const float* __restrict__ alpha, const float* __restrict__ x) {
    const int tid = threadIdx.x;
    if (blockIdx.x < COUT) {
        const int co = blockIdx.x, ci = tid;
        const float r0 = RV[0], r1 = RV[1], r2 = RV[2], r3 = RV[3];
        const size_t ks = (size_t)COUT * CIN * 9;
        const float* w0 = Wt + ((size_t)co * CIN + ci) * 9;
        float acc = 0.f;
#pragma unroll
        for (int t = 0; t < 9; t++) {
            float rw = r0 * w0[t] + r1 * w0[t + ks] + r2 * w0[t + 2 * ks] + r3 * w0[t + 3 * ks];
            acc += fabsf(rw);
            float s = (rw > 0.f) ? 1.f : ((rw < 0.f) ? -1.f : 0.f);
            g_wb[((size_t)t * COUT + co) * CIN + ci] = __float2bfloat16(s);
        }
        __shared__ float red[256];
        red[ci] = acc;
        __syncthreads();
        for (int st = 128; st > 0; st >>= 1) {
            if (ci < st) red[ci] += red[ci + st];
            __syncthreads();
        }
        if (ci == 0) g_sa[co] = alpha[co] * (red[0] * (1.0f / 2304.0f));
    } else {
        const int id = blockIdx.x - COUT;
        const int cc = id & 3;             // channel chunk (64 ch)
        const int h  = (id >> 2) % H_;
        const int b  = (id >> 2) / H_;
        __shared__ __nv_bfloat16 sb[64 * 56];  // [ci][w]
        const float* xp = x + (((size_t)b * CIN + cc * 64) * H_ + h) * W_;
        for (int i = tid; i < 64 * 56; i += 256) {
            int ci = i / 56, w = i - ci * 56;
            float v = xp[(size_t)ci * (H_ * W_) + w];
            float s = (v > 0.f) ? 1.f : ((v < 0.f) ? -1.f : 0.f);
            sb[ci * 56 + w] = __float2bfloat16(s);
        }
        __syncthreads();
        __nv_bfloat16* dst0 = g_xb + (((size_t)b * HP + (h + 1)) * WP + 1) * CIN + cc * 64;
        for (int u = tid; u < 56 * 8; u += 256) {
            int w = u >> 3, s8 = (u & 7) * 8;
            uint32_t v4[4];
#pragma unroll
            for (int jp = 0; jp < 4; jp++) {
                __nv_bfloat16 lo = sb[(s8 + 2 * jp) * 56 + w];
                __nv_bfloat16 hi = sb[(s8 + 2 * jp + 1) * 56 + w];
                unsigned short rl = *reinterpret_cast<unsigned short*>(&lo);
                unsigned short rh = *reinterpret_cast<unsigned short*>(&hi);
                v4[jp] = (uint32_t)rl | ((uint32_t)rh << 16);
            }
            *reinterpret_cast<uint4*>(dst0 + (size_t)w * CIN + s8) =
                make_uint4(v4[0], v4[1], v4[2], v4[3]);
        }
    }
}

// ---------------- main GEMM kernel ----------------
#define NSTG     3
#define A_BYTES  16384                 // 128 rows x 128B
#define STG      32768                 // A(16K) + B(16K) per stage
#define GSMEM    (NSTG * STG)          // 98304 B -> 2 CTAs/SM
#define NCHUNK   36                    // 9 taps x 4 ci-chunks of 64

__global__ void __launch_bounds__(256, 2) bconv_gemm(float* __restrict__ out) {
    extern __shared__ char smem[];
    const uint32_t sbase = smem_u32(smem);
    const int tid  = threadIdx.x;
    const int warp = tid >> 5, lane = tid & 31;
    const int mw = warp >> 1;          // 0..3: M rows 32*mw..+31
    const int nw = warp & 1;           // 0..1: N cols 64*nw..+63 (within 128-half)
    const int bidx  = blockIdx.x;
    const int co0   = (bidx & 1) * 128;
    const int mtile = bidx >> 1;
    const int b  = mtile / 28;
    const int h0 = (mtile - b * 28) * 2;

    const int seg = tid & 7;   // 16B segment within 128B k-row
    const int rb  = tid >> 3;  // base row 0..31

    const int rlo   = lane & 15;
    const int khalf = (lane >> 4) << 4;        // 0 or 16 bytes
    const int swz   = (rlo & 7) << 4;

    float d[2][8][4];
#pragma unroll
    for (int mi = 0; mi < 2; mi++)
#pragma unroll
        for (int ni = 0; ni < 8; ni++)
#pragma unroll
            for (int j = 0; j < 4; j++) d[mi][ni][j] = 0.f;

    auto load_chunk = [&](int chunk, int stage) {
        const int t  = chunk >> 2;                 // tap 0..8
        const int cc = (chunk & 3) << 6;           // ci chunk base
        const int kh = t / 3, kw = t - kh * 3;
        const uint32_t stgA = sbase + stage * STG;
        const uint32_t stgB = stgA + A_BYTES;
        const __nv_bfloat16* abase =
            g_xb + (((size_t)b * HP + (h0 + kh)) * WP + kw) * CIN + cc;
#pragma unroll
        for (int k = 0; k < 4; k++) {
            int r  = rb + 32 * k;
            int rc = (r < 112) ? r : 111;          // rows 112-127 dummy
            int ha = (rc >= 56) ? 1 : 0;
            int w  = rc - 56 * ha;
            const char* src = (const char*)(abase + ((size_t)ha * WP + w) * CIN) + seg * 16;
            CP16(stgA + r * 128 + ((seg * 16) ^ ((r & 7) << 4)), src);
        }
        const char* bsrc = (const char*)(g_wb + ((size_t)t * COUT + co0) * CIN + cc);
#pragma unroll
        for (int k = 0; k < 4; k++) {
            int r = rb + 32 * k;
            const char* src = bsrc + (size_t)r * (CIN * 2) + seg * 16;
            CP16(stgB + r * 128 + ((seg * 16) ^ ((r & 7) << 4)), src);
        }
    };

    load_chunk(0, 0); CP_COMMIT();
    load_chunk(1, 1); CP_COMMIT();

    const int rowA0 = 32 * mw + rlo;
    const int rowB0 = 64 * nw + rlo;

    for (int i = 0; i < NCHUNK; i++) {
        CP_WAIT(1);
        __syncthreads();
        if (i + 2 < NCHUNK) load_chunk(i + 2, (i + 2) % 3);
        CP_COMMIT();

        const uint32_t stgA = sbase + (i % 3) * STG;
        const uint32_t stgB = stgA + A_BYTES;
#pragma unroll
        for (int ks = 0; ks < 4; ks++) {
            const int kb = ks * 32 + khalf;
            // batch all 6 ldmatrix first, then the 16 MMAs (hide LDS latency)
            uint32_t a[2][4], bf[4][4];
            LDSM4(a[0], stgA + rowA0 * 128 + (kb ^ swz));
            LDSM4(a[1], stgA + (rowA0 + 16) * 128 + (kb ^ swz));
#pragma unroll
            for (int np = 0; np < 4; np++)
                LDSM4(bf[np], stgB + (rowB0 + 16 * np) * 128 + (kb ^ swz));
#pragma unroll
            for (int np = 0; np < 4; np++) {
                MMA16816(d[0][2 * np],     a[0], bf[np][0], bf[np][2]);
                MMA16816(d[0][2 * np + 1], a[0], bf[np][1], bf[np][3]);
                MMA16816(d[1][2 * np],     a[1], bf[np][0], bf[np][2]);
                MMA16816(d[1][2 * np + 1], a[1], bf[np][1], bf[np][3]);
            }
        }
    }

    CP_WAIT(0);
    __syncthreads();

    // ---------------- epilogue: stage through SMEM, coalesced stores ----------------
    float* buf = (float*)smem;                 // 64 cl x 128 rows = 32KB
    const int q  = lane & 3;
    const int rr = lane >> 2;
#pragma unroll 1
    for (int hh = 0; hh < 2; hh++) {
        if (nw == hh) {
#pragma unroll
            for (int mi = 0; mi < 2; mi++)
#pragma unroll
                for (int ni = 0; ni < 8; ni++) {
                    int cl  = 8 * ni + 2 * q;
                    int row = 32 * mw + 16 * mi + rr;
                    buf[cl * 128 + row]           = d[mi][ni][0];
                    buf[(cl + 1) * 128 + row]     = d[mi][ni][1];
                    buf[cl * 128 + row + 8]       = d[mi][ni][2];
                    buf[(cl + 1) * 128 + row + 8] = d[mi][ni][3];
                }
        }
        __syncthreads();
        for (int it = 0; it < 28; it++) {
            int u  = tid + 256 * it;           // 0..7167
            int cl = u / 112;
            int r  = u - cl * 112;
            int ha = (r >= 56) ? 1 : 0;
            int w  = r - 56 * ha;
            int co = co0 + hh * 64 + cl;
            float sa = __ldg(&g_sa[co]);
            out[(((size_t)b * COUT + co) * H_ + (h0 + ha)) * W_ + w] =
                buf[cl * 128 + r] * sa;
        }
        __syncthreads();
    }
}

// ---------------- launch ----------------
extern "C" void kernel_launch(void* const* d_in, const int* in_sizes, int n_in,
                              void* d_out, int out_size) {
    const float* x     = (const float*)d_in[0];  // [32,256,56,56]
    const float* wts   = (const float*)d_in[1];  // [4,256,256,3,3]
    const float* rv    = (const float*)d_in[2];  // [5]
    const float* alpha = (const float*)d_in[3];  // [256]
    float* out = (float*)d_out;

    cudaFuncSetAttribute(bconv_gemm, cudaFuncAttributeMaxDynamicSharedMemorySize, GSMEM);

    prep_all<<<COUT + 4 * H_ * B_, 256>>>(wts, rv, alpha, x);
    bconv_gemm<<<B_ * (H_ / 2) * 2, 256, GSMEM>>>(out);
}

// round 4
// speedup vs baseline: 1.2306x; 1.0623x over previous
#include <cuda_runtime.h>
#include <cstdint>

// ============================================================
// BinarizeConv2d: out = conv3x3(sign(x), sign(mix(W))) * scale * alpha
// Implicit GEMM on mma.sync m16n8k32 FP8 e4m3 (exact for ±1), sm_100.
//   M-tile 128 (2 h-rows x 56 w, 112 valid), N-tile 128, K = 2304
//   18 chunks of K=128 (tap x 128-ci), 3-stage cp.async, 2 CTAs/SM.
// ============================================================

#define B_   32
#define CIN  256
#define COUT 256
#define H_   56
#define W_   56
#define HP   58
#define WP   58

// e4m3 encodings of {+1,-1,0}: 0x38, 0xB8, 0x00
__device__ uint8_t g_xb[(size_t)B_ * HP * WP * CIN];  // sign(x), NHWC padded (borders stay 0)
__device__ uint8_t g_wb[9 * COUT * CIN];              // sign(real_w) [tap][co][ci]
__device__ float   g_sa[COUT];                        // alpha * scale

// ---------------- PTX helpers ----------------
__device__ __forceinline__ uint32_t smem_u32(const void* p) {
    uint32_t a;
    asm("{ .reg .u64 t; cvta.to.shared.u64 t, %1; cvt.u32.u64 %0, t; }" : "=r"(a) : "l"(p));
    return a;
}
#define CP16(d, s)   asm volatile("cp.async.cg.shared.global [%0], [%1], 16;" :: "r"(d), "l"(s) : "memory")
#define CP_COMMIT()  asm volatile("cp.async.commit_group;" ::: "memory")
#define CP_WAIT(n)   asm volatile("cp.async.wait_group %0;" :: "n"(n) : "memory")

#define LDSM4(r, a)                                                          \
    asm volatile("ldmatrix.sync.aligned.m8n8.x4.shared.b16 {%0,%1,%2,%3}, [%4];" \
        : "=r"((r)[0]), "=r"((r)[1]), "=r"((r)[2]), "=r"((r)[3]) : "r"(a))

// FP8 e4m3 MMA, K=32, fp32 accum. Reg layout matches ldmatrix.x4.b16 output:
// each 32-bit reg holds 4 consecutive fp8 k-values.
#define MMA16832(d, a, b0, b1)                                               \
    asm volatile("mma.sync.aligned.m16n8k32.row.col.f32.e4m3.e4m3.f32 "      \
        "{%0,%1,%2,%3}, {%4,%5,%6,%7}, {%8,%9}, {%0,%1,%2,%3};"              \
        : "+f"((d)[0]), "+f"((d)[1]), "+f"((d)[2]), "+f"((d)[3])             \
        : "r"((a)[0]), "r"((a)[1]), "r"((a)[2]), "r"((a)[3]),                \
          "r"(b0), "r"(b1))

__device__ __forceinline__ uint8_t sign_e4m3(float v) {
    return (v > 0.f) ? 0x38 : ((v < 0.f) ? 0xB8 : 0x00);
}

// ---------------- merged prep kernel ----------------
// blocks [0,256):          weight mix/sign/scale  (co = blockIdx.x)
// blocks [256,256+7168):   binarize x, NCHW -> padded NHWC fp8
__global__ void prep_all(const float* __restrict__ Wt, const float* __restrict__ RV,
                         const float* __restrict__ alpha, const float* __restrict__ x) {
    const int tid = threadIdx.x;
    if (blockIdx.x < COUT) {
        const int co = blockIdx.x, ci = tid;
        const float r0 = RV[0], r1 = RV[1], r2 = RV[2], r3 = RV[3];
        const size_t ks = (size_t)COUT * CIN * 9;
        const float* w0 = Wt + ((size_t)co * CIN + ci) * 9;
        float acc = 0.f;
#pragma unroll
        for (int t = 0; t < 9; t++) {
            float rw = r0 * w0[t] + r1 * w0[t + ks] + r2 * w0[t + 2 * ks] + r3 * w0[t + 3 * ks];
            acc += fabsf(rw);
            g_wb[((size_t)t * COUT + co) * CIN + ci] = sign_e4m3(rw);
        }
        __shared__ float red[256];
        red[ci] = acc;
        __syncthreads();
        for (int st = 128; st > 0; st >>= 1) {
            if (ci < st) red[ci] += red[ci + st];
            __syncthreads();
        }
        if (ci == 0) g_sa[co] = alpha[co] * (red[0] * (1.0f / 2304.0f));
    } else {
        const int id = blockIdx.x - COUT;
        const int cc = id & 3;             // 64-ci chunk
        const int h  = (id >> 2) % H_;
        const int b  = (id >> 2) / H_;
        __shared__ __align__(16) uint8_t sb[56 * 64];  // [w][ci]
        const float* xp = x + (((size_t)b * CIN + cc * 64) * H_ + h) * W_;
        for (int i = tid; i < 64 * 56; i += 256) {
            int ci = i / 56, w = i - ci * 56;          // consecutive tid -> consecutive w
            sb[w * 64 + ci] = sign_e4m3(xp[(size_t)ci * (H_ * W_) + w]);
        }
        __syncthreads();
        uint8_t* dst0 = g_xb + (((size_t)b * HP + (h + 1)) * WP + 1) * CIN + cc * 64;
        for (int u = tid; u < 56 * 4; u += 256) {
            int w = u >> 2, s16 = (u & 3) * 16;
            *reinterpret_cast<uint4*>(dst0 + (size_t)w * CIN + s16) =
                *reinterpret_cast<const uint4*>(sb + w * 64 + s16);
        }
    }
}

// ---------------- main GEMM kernel ----------------
#define NSTG     3
#define A_BYTES  16384                 // 128 rows x 128B (128 fp8 ci)
#define STG      32768                 // A(16K) + B(16K) per stage
#define GSMEM    (NSTG * STG)          // 98304 B -> 2 CTAs/SM
#define NCHUNK   18                    // 9 taps x 2 ci-chunks of 128

__global__ void __launch_bounds__(256, 2) bconv_gemm(float* __restrict__ out) {
    extern __shared__ char smem[];
    const uint32_t sbase = smem_u32(smem);
    const int tid  = threadIdx.x;
    const int warp = tid >> 5, lane = tid & 31;
    const int mw = warp >> 1;          // 0..3: M rows 32*mw..+31
    const int nw = warp & 1;           // 0..1: N cols 64*nw..+63 (within 128-half)
    const int bidx  = blockIdx.x;
    const int co0   = (bidx & 1) * 128;
    const int mtile = bidx >> 1;
    const int b  = mtile / 28;
    const int h0 = (mtile - b * 28) * 2;

    const int seg = tid & 7;   // 16B segment within 128B k-row
    const int rb  = tid >> 3;  // base row 0..31

    const int rlo   = lane & 15;
    const int khalf = (lane >> 4) << 4;        // 0 or 16 bytes
    const int swz   = (rlo & 7) << 4;

    float d[2][8][4];
#pragma unroll
    for (int mi = 0; mi < 2; mi++)
#pragma unroll
        for (int ni = 0; ni < 8; ni++)
#pragma unroll
            for (int j = 0; j < 4; j++) d[mi][ni][j] = 0.f;

    auto load_chunk = [&](int chunk, int stage) {
        const int t  = chunk >> 1;                 // tap 0..8
        const int cc = (chunk & 1) << 7;           // ci chunk base (0 or 128)
        const int kh = t / 3, kw = t - kh * 3;
        const uint32_t stgA = sbase + stage * STG;
        const uint32_t stgB = stgA + A_BYTES;
        const uint8_t* abase =
            g_xb + (((size_t)b * HP + (h0 + kh)) * WP + kw) * CIN + cc;
#pragma unroll
        for (int k = 0; k < 4; k++) {
            int r  = rb + 32 * k;
            int rc = (r < 112) ? r : 111;          // rows 112-127 dummy
            int ha = (rc >= 56) ? 1 : 0;
            int w  = rc - 56 * ha;
            const char* src = (const char*)(abase + ((size_t)ha * WP + w) * CIN) + seg * 16;
            CP16(stgA + r * 128 + ((seg * 16) ^ ((r & 7) << 4)), src);
        }
        const uint8_t* bsrc = g_wb + ((size_t)t * COUT + co0) * CIN + cc;
#pragma unroll
        for (int k = 0; k < 4; k++) {
            int r = rb + 32 * k;
            const char* src = (const char*)(bsrc + (size_t)r * CIN) + seg * 16;
            CP16(stgB + r * 128 + ((seg * 16) ^ ((r & 7) << 4)), src);
        }
    };

    load_chunk(0, 0); CP_COMMIT();
    load_chunk(1, 1); CP_COMMIT();

    const int rowA0 = 32 * mw + rlo;
    const int rowB0 = 64 * nw + rlo;

    for (int i = 0; i < NCHUNK; i++) {
        CP_WAIT(1);
        __syncthreads();
        if (i + 2 < NCHUNK) load_chunk(i + 2, (i + 2) % 3);
        CP_COMMIT();

        const uint32_t stgA = sbase + (i % 3) * STG;
        const uint32_t stgB = stgA + A_BYTES;
#pragma unroll
        for (int ks = 0; ks < 4; ks++) {           // 4 x k32 within the 128B row
            const int kb = ks * 32 + khalf;
            uint32_t a[2][4], bf[4][4];
            LDSM4(a[0], stgA + rowA0 * 128 + (kb ^ swz));
            LDSM4(a[1], stgA + (rowA0 + 16) * 128 + (kb ^ swz));
#pragma unroll
            for (int np = 0; np < 4; np++)
                LDSM4(bf[np], stgB + (rowB0 + 16 * np) * 128 + (kb ^ swz));
#pragma unroll
            for (int np = 0; np < 4; np++) {
                MMA16832(d[0][2 * np],     a[0], bf[np][0], bf[np][2]);
                MMA16832(d[0][2 * np + 1], a[0], bf[np][1], bf[np][3]);
                MMA16832(d[1][2 * np],     a[1], bf[np][0], bf[np][2]);
                MMA16832(d[1][2 * np + 1], a[1], bf[np][1], bf[np][3]);
            }
        }
    }

    CP_WAIT(0);
    __syncthreads();

    // ---------------- epilogue: stage through SMEM, coalesced stores ----------------
    float* buf = (float*)smem;                 // 64 cl x 128 rows = 32KB
    const int q  = lane & 3;
    const int rr = lane >> 2;
#pragma unroll 1
    for (int hh = 0; hh < 2; hh++) {
        if (nw == hh) {
#pragma unroll
            for (int mi = 0; mi < 2; mi++)
#pragma unroll
                for (int ni = 0; ni < 8; ni++) {
                    int cl  = 8 * ni + 2 * q;
                    int row = 32 * mw + 16 * mi + rr;
                    buf[cl * 128 + row]           = d[mi][ni][0];
                    buf[(cl + 1) * 128 + row]     = d[mi][ni][1];
                    buf[cl * 128 + row + 8]       = d[mi][ni][2];
                    buf[(cl + 1) * 128 + row + 8] = d[mi][ni][3];
                }
        }
        __syncthreads();
        for (int it = 0; it < 28; it++) {
            int u  = tid + 256 * it;           // 0..7167
            int cl = u / 112;
            int r  = u - cl * 112;
            int ha = (r >= 56) ? 1 : 0;
            int w  = r - 56 * ha;
            int co = co0 + hh * 64 + cl;
            float sa = __ldg(&g_sa[co]);
            out[(((size_t)b * COUT + co) * H_ + (h0 + ha)) * W_ + w] =
                buf[cl * 128 + r] * sa;
        }
        __syncthreads();
    }
}

// ---------------- launch ----------------
extern "C" void kernel_launch(void* const* d_in, const int* in_sizes, int n_in,
                              void* d_out, int out_size) {
    const float* x     = (const float*)d_in[0];  // [32,256,56,56]
    const float* wts   = (const float*)d_in[1];  // [4,256,256,3,3]
    const float* rv    = (const float*)d_in[2];  // [5]
    const float* alpha = (const float*)d_in[3];  // [256]
    float* out = (float*)d_out;

    cudaFuncSetAttribute(bconv_gemm, cudaFuncAttributeMaxDynamicSharedMemorySize, GSMEM);

    prep_all<<<COUT + 4 * H_ * B_, 256>>>(wts, rv, alpha, x);
    bconv_gemm<<<B_ * (H_ / 2) * 2, 256, GSMEM>>>(out);
}

// round 6
// speedup vs baseline: 1.4957x; 1.2154x over previous
#include <cuda_runtime.h>
#include <cstdint>

// ============================================================
// BinarizeConv2d: out = conv3x3(sign(x), sign(mix(W))) * scale * alpha
// Implicit GEMM, mma.sync m16n8k32 FP8 e4m3 (exact for ±1), sm_100.
// R5 (resubmit; R5 bench was an infra failure, kernel never ran):
//   M flattened over B*H*W = 784 x 128 exact tiles (no M waste),
//   hoisted per-chunk addressing, table-driven epilogue.
// ============================================================

#define B_   32
#define CIN  256
#define COUT 256
#define H_   56
#define W_   56
#define HP   58
#define WP   58
#define HW   3136      // 56*56

// e4m3 encodings of {+1,-1,0}: 0x38, 0xB8, 0x00
__device__ uint8_t g_xb[(size_t)B_ * HP * WP * CIN];  // sign(x), NHWC padded (borders stay 0)
__device__ uint8_t g_wb[9 * COUT * CIN];              // sign(real_w) [tap][co][ci]
__device__ float   g_sa[COUT];                        // alpha * scale

// ---------------- PTX helpers ----------------
__device__ __forceinline__ uint32_t smem_u32(const void* p) {
    uint32_t a;
    asm("{ .reg .u64 t; cvta.to.shared.u64 t, %1; cvt.u32.u64 %0, t; }" : "=r"(a) : "l"(p));
    return a;
}
#define CP16(d, s)   asm volatile("cp.async.cg.shared.global [%0], [%1], 16;" :: "r"(d), "l"(s) : "memory")
#define CP_COMMIT()  asm volatile("cp.async.commit_group;" ::: "memory")
#define CP_WAIT(n)   asm volatile("cp.async.wait_group %0;" :: "n"(n) : "memory")

#define LDSM4(r, a)                                                          \
    asm volatile("ldmatrix.sync.aligned.m8n8.x4.shared.b16 {%0,%1,%2,%3}, [%4];" \
        : "=r"((r)[0]), "=r"((r)[1]), "=r"((r)[2]), "=r"((r)[3]) : "r"(a))

#define MMA16832(d, a, b0, b1)                                               \
    asm volatile("mma.sync.aligned.m16n8k32.row.col.f32.e4m3.e4m3.f32 "      \
        "{%0,%1,%2,%3}, {%4,%5,%6,%7}, {%8,%9}, {%0,%1,%2,%3};"              \
        : "+f"((d)[0]), "+f"((d)[1]), "+f"((d)[2]), "+f"((d)[3])             \
        : "r"((a)[0]), "r"((a)[1]), "r"((a)[2]), "r"((a)[3]),                \
          "r"(b0), "r"(b1))

__device__ __forceinline__ uint8_t sign_e4m3(float v) {
    return (v > 0.f) ? 0x38 : ((v < 0.f) ? 0xB8 : 0x00);
}

// ---------------- merged prep kernel ----------------
__global__ void prep_all(const float* __restrict__ Wt, const float* __restrict__ RV,
                         const float* __restrict__ alpha, const float* __restrict__ x) {
    const int tid = threadIdx.x;
    if (blockIdx.x < COUT) {
        const int co = blockIdx.x, ci = tid;
        const float r0 = RV[0], r1 = RV[1], r2 = RV[2], r3 = RV[3];
        const size_t ks = (size_t)COUT * CIN * 9;
        const float* w0 = Wt + ((size_t)co * CIN + ci) * 9;
        float acc = 0.f;
#pragma unroll
        for (int t = 0; t < 9; t++) {
            float rw = r0 * w0[t] + r1 * w0[t + ks] + r2 * w0[t + 2 * ks] + r3 * w0[t + 3 * ks];
            acc += fabsf(rw);
            g_wb[((size_t)t * COUT + co) * CIN + ci] = sign_e4m3(rw);
        }
        __shared__ float red[256];
        red[ci] = acc;
        __syncthreads();
        for (int st = 128; st > 0; st >>= 1) {
            if (ci < st) red[ci] += red[ci + st];
            __syncthreads();
        }
        if (ci == 0) g_sa[co] = alpha[co] * (red[0] * (1.0f / 2304.0f));
    } else {
        const int id = blockIdx.x - COUT;
        const int cc = id & 3;             // 64-ci chunk
        const int h  = (id >> 2) % H_;
        const int b  = (id >> 2) / H_;
        __shared__ __align__(16) uint8_t sb[56 * 64];  // [w][ci]
        const float* xp = x + (((size_t)b * CIN + cc * 64) * H_ + h) * W_;
        for (int i = tid; i < 64 * 56; i += 256) {
            int ci = i / 56, w = i - ci * 56;
            sb[w * 64 + ci] = sign_e4m3(xp[(size_t)ci * (H_ * W_) + w]);
        }
        __syncthreads();
        uint8_t* dst0 = g_xb + (((size_t)b * HP + (h + 1)) * WP + 1) * CIN + cc * 64;
        for (int u = tid; u < 56 * 4; u += 256) {
            int w = u >> 2, s16 = (u & 3) * 16;
            *reinterpret_cast<uint4*>(dst0 + (size_t)w * CIN + s16) =
                *reinterpret_cast<const uint4*>(sb + w * 64 + s16);
        }
    }
}

// ---------------- main GEMM kernel ----------------
#define NSTG     3
#define A_BYTES  16384                 // 128 rows x 128B (128 fp8 ci)
#define STG      32768                 // A(16K) + B(16K)
#define GSMEM    (NSTG * STG)          // 98304 B -> 2 CTAs/SM
#define NCHUNK   18                    // 9 taps x 2 ci-chunks of 128

__global__ void __launch_bounds__(256, 2) bconv_gemm(float* __restrict__ out) {
    extern __shared__ char smem[];
    const uint32_t sbase = smem_u32(smem);
    const int tid  = threadIdx.x;
    const int warp = tid >> 5, lane = tid & 31;
    const int mw = warp >> 1;          // 0..3: M rows 32*mw..+31
    const int nw = warp & 1;           // 0..1: N cols 64*nw..+63
    const int bidx = blockIdx.x;
    const int co0  = (bidx & 1) * 128;
    const int m0   = (bidx >> 1) << 7;   // global M base, tiles exact (784*128 = 100352)

    const int seg = tid & 7;   // 16B segment within 128B k-row
    const int rb  = tid >> 3;  // base row 0..31

    // ---- hoisted load addressing (loop-invariant per chunk) ----
    int aoff[4];
#pragma unroll
    for (int k = 0; k < 4; k++) {
        int m = m0 + rb + 32 * k;
        int ib  = m / HW;
        int rem = m - ib * HW;
        int h = rem / W_, w = rem - h * W_;
        aoff[k] = ((ib * HP + h) * WP + w) * CIN + seg * 16;
    }
    int boff[4];
#pragma unroll
    for (int k = 0; k < 4; k++) boff[k] = (co0 + rb + 32 * k) * CIN + seg * 16;
    // smem dst: swizzle constant per thread ((rb&7) invariant over k)
    const uint32_t dstb = rb * 128 + ((seg * 16) ^ ((rb & 7) << 4));

    const int rlo   = lane & 15;
    const int khalf = (lane >> 4) << 4;
    const int swz   = (rlo & 7) << 4;

    float d[2][8][4];
#pragma unroll
    for (int mi = 0; mi < 2; mi++)
#pragma unroll
        for (int ni = 0; ni < 8; ni++)
#pragma unroll
            for (int j = 0; j < 4; j++) d[mi][ni][j] = 0.f;

    auto load_chunk = [&](int chunk, int stage) {
        const int t  = chunk >> 1;                 // tap 0..8
        const int cc = (chunk & 1) << 7;           // ci base (0 or 128)
        const int kh = t / 3, kw = t - kh * 3;
        const int toffA = (kh * WP + kw) * CIN + cc;
        const int toffB = t * (COUT * CIN) + cc;
        const uint32_t stgA = sbase + stage * STG + dstb;
        const uint32_t stgB = stgA + A_BYTES;
#pragma unroll
        for (int k = 0; k < 4; k++)
            CP16(stgA + k * 4096, (const char*)g_xb + aoff[k] + toffA);
#pragma unroll
        for (int k = 0; k < 4; k++)
            CP16(stgB + k * 4096, (const char*)g_wb + boff[k] + toffB);
    };

    load_chunk(0, 0); CP_COMMIT();
    load_chunk(1, 1); CP_COMMIT();

    const int rowA0 = 32 * mw + rlo;
    const int rowB0 = 64 * nw + rlo;

    int stage = 2;                 // stage to fill next
    for (int i = 0; i < NCHUNK; i++) {
        CP_WAIT(1);
        __syncthreads();
        if (i + 2 < NCHUNK) load_chunk(i + 2, stage);
        CP_COMMIT();

        const int cur = (stage == 2) ? 0 : stage + 1;   // = i % 3
        stage = cur;
        const uint32_t stgA = sbase + cur * STG;
        const uint32_t stgB = stgA + A_BYTES;
#pragma unroll
        for (int ks = 0; ks < 4; ks++) {
            const int kb = ks * 32 + khalf;
            uint32_t a[2][4], bf[4][4];
            LDSM4(a[0], stgA + rowA0 * 128 + (kb ^ swz));
            LDSM4(a[1], stgA + (rowA0 + 16) * 128 + (kb ^ swz));
#pragma unroll
            for (int np = 0; np < 4; np++)
                LDSM4(bf[np], stgB + (rowB0 + 16 * np) * 128 + (kb ^ swz));
#pragma unroll
            for (int np = 0; np < 4; np++) {
                MMA16832(d[0][2 * np],     a[0], bf[np][0], bf[np][2]);
                MMA16832(d[0][2 * np + 1], a[0], bf[np][1], bf[np][3]);
                MMA16832(d[1][2 * np],     a[1], bf[np][0], bf[np][2]);
                MMA16832(d[1][2 * np + 1], a[1], bf[np][1], bf[np][3]);
            }
        }
    }

    CP_WAIT(0);
    __syncthreads();

    // ---------------- epilogue ----------------
    float* buf    = (float*)smem;                  // 64 cl x 128 rows = 32KB
    int*   stable = (int*)(smem + 40960);          // 128-entry row -> out offset (co=0)
    if (tid < 128) {
        int m = m0 + tid;
        int ib  = m / HW;
        int rem = m - ib * HW;
        stable[tid] = ib * (COUT * HW) + rem;      // + co*HW gives final offset
    }
    const int q  = lane & 3;
    const int rr = lane >> 2;
#pragma unroll 1
    for (int hh = 0; hh < 2; hh++) {
        if (nw == hh) {
#pragma unroll
            for (int mi = 0; mi < 2; mi++)
#pragma unroll
                for (int ni = 0; ni < 8; ni++) {
                    int cl  = 8 * ni + 2 * q;
                    int row = 32 * mw + 16 * mi + rr;
                    buf[cl * 128 + row]           = d[mi][ni][0];
                    buf[(cl + 1) * 128 + row]     = d[mi][ni][1];
                    buf[cl * 128 + row + 8]       = d[mi][ni][2];
                    buf[(cl + 1) * 128 + row + 8] = d[mi][ni][3];
                }
        }
        __syncthreads();
#pragma unroll 4
        for (int it = 0; it < 32; it++) {
            int u  = tid + 256 * it;               // 0..8191
            int cl = u >> 7;
            int r  = u & 127;
            int co = co0 + hh * 64 + cl;
            out[stable[r] + co * HW] = buf[cl * 128 + r] * __ldg(&g_sa[co]);
        }
        __syncthreads();
    }
}

// ---------------- launch ----------------
extern "C" void kernel_launch(void* const* d_in, const int* in_sizes, int n_in,
                              void* d_out, int out_size) {
    const float* x     = (const float*)d_in[0];  // [32,256,56,56]
    const float* wts   = (const float*)d_in[1];  // [4,256,256,3,3]
    const float* rv    = (const float*)d_in[2];  // [5]
    const float* alpha = (const float*)d_in[3];  // [256]
    float* out = (float*)d_out;

    cudaFuncSetAttribute(bconv_gemm, cudaFuncAttributeMaxDynamicSharedMemorySize, GSMEM);

    prep_all<<<COUT + 4 * H_ * B_, 256>>>(wts, rv, alpha, x);
    bconv_gemm<<<784 * 2, 256, GSMEM>>>(out);
}

// round 7
// speedup vs baseline: 2.3249x; 1.5543x over previous
#include <cuda_runtime.h>
#include <cstdint>

// ============================================================
// BinarizeConv2d: out = conv3x3(sign(x), sign(mix(W))) * scale * alpha
// Implicit GEMM, mma.sync m16n8k32 INT8 s8s8s32 (exact for ±1), sm_100.
// R7: int8 tensor path (2x MAC rate vs fp16/fp8 on legacy mma.sync).
//   M flattened over B*H*W = 784 x 128 exact tiles, N-tile 128,
//   18 chunks of K=128, 3-stage cp.async, 2 CTAs/SM.
// ============================================================

#define B_   32
#define CIN  256
#define COUT 256
#define H_   56
#define W_   56
#define HP   58
#define WP   58
#define HW   3136      // 56*56

// int8 encodings of {+1,-1,0}: 0x01, 0xFF, 0x00
__device__ uint8_t g_xb[(size_t)B_ * HP * WP * CIN];  // sign(x), NHWC padded (borders stay 0)
__device__ uint8_t g_wb[9 * COUT * CIN];              // sign(real_w) [tap][co][ci]
__device__ float   g_sa[COUT];                        // alpha * scale

// ---------------- PTX helpers ----------------
__device__ __forceinline__ uint32_t smem_u32(const void* p) {
    uint32_t a;
    asm("{ .reg .u64 t; cvta.to.shared.u64 t, %1; cvt.u32.u64 %0, t; }" : "=r"(a) : "l"(p));
    return a;
}
#define CP16(d, s)   asm volatile("cp.async.cg.shared.global [%0], [%1], 16;" :: "r"(d), "l"(s) : "memory")
#define CP_COMMIT()  asm volatile("cp.async.commit_group;" ::: "memory")
#define CP_WAIT(n)   asm volatile("cp.async.wait_group %0;" :: "n"(n) : "memory")

#define LDSM4(r, a)                                                          \
    asm volatile("ldmatrix.sync.aligned.m8n8.x4.shared.b16 {%0,%1,%2,%3}, [%4];" \
        : "=r"((r)[0]), "=r"((r)[1]), "=r"((r)[2]), "=r"((r)[3]) : "r"(a))

// INT8 MMA, K=32, s32 accum. Same fragment layout as fp8 k32
// (each 32-bit reg = 4 consecutive int8 k-values from ldmatrix.b16).
#define MMAI(d, a, b0, b1)                                                   \
    asm volatile("mma.sync.aligned.m16n8k32.row.col.s32.s8.s8.s32 "          \
        "{%0,%1,%2,%3}, {%4,%5,%6,%7}, {%8,%9}, {%0,%1,%2,%3};"              \
        : "+r"((d)[0]), "+r"((d)[1]), "+r"((d)[2]), "+r"((d)[3])             \
        : "r"((a)[0]), "r"((a)[1]), "r"((a)[2]), "r"((a)[3]),                \
          "r"(b0), "r"(b1))

__device__ __forceinline__ uint8_t sign_s8(float v) {
    return (v > 0.f) ? 0x01 : ((v < 0.f) ? 0xFF : 0x00);
}

// ---------------- merged prep kernel ----------------
__global__ void prep_all(const float* __restrict__ Wt, const float* __restrict__ RV,
                         const float* __restrict__ alpha, const float* __restrict__ x) {
    const int tid = threadIdx.x;
    if (blockIdx.x < COUT) {
        const int co = blockIdx.x, ci = tid;
        const float r0 = RV[0], r1 = RV[1], r2 = RV[2], r3 = RV[3];
        const size_t ks = (size_t)COUT * CIN * 9;
        const float* w0 = Wt + ((size_t)co * CIN + ci) * 9;
        float acc = 0.f;
#pragma unroll
        for (int t = 0; t < 9; t++) {
            float rw = r0 * w0[t] + r1 * w0[t + ks] + r2 * w0[t + 2 * ks] + r3 * w0[t + 3 * ks];
            acc += fabsf(rw);
            g_wb[((size_t)t * COUT + co) * CIN + ci] = sign_s8(rw);
        }
        __shared__ float red[256];
        red[ci] = acc;
        __syncthreads();
        for (int st = 128; st > 0; st >>= 1) {
            if (ci < st) red[ci] += red[ci + st];
            __syncthreads();
        }
        if (ci == 0) g_sa[co] = alpha[co] * (red[0] * (1.0f / 2304.0f));
    } else {
        const int id = blockIdx.x - COUT;
        const int cc = id & 3;             // 64-ci chunk
        const int h  = (id >> 2) % H_;
        const int b  = (id >> 2) / H_;
        __shared__ __align__(16) uint8_t sb[56 * 64];  // [w][ci]
        const float* xp = x + (((size_t)b * CIN + cc * 64) * H_ + h) * W_;
        for (int i = tid; i < 64 * 56; i += 256) {
            int ci = i / 56, w = i - ci * 56;
            sb[w * 64 + ci] = sign_s8(xp[(size_t)ci * (H_ * W_) + w]);
        }
        __syncthreads();
        uint8_t* dst0 = g_xb + (((size_t)b * HP + (h + 1)) * WP + 1) * CIN + cc * 64;
        for (int u = tid; u < 56 * 4; u += 256) {
            int w = u >> 2, s16 = (u & 3) * 16;
            *reinterpret_cast<uint4*>(dst0 + (size_t)w * CIN + s16) =
                *reinterpret_cast<const uint4*>(sb + w * 64 + s16);
        }
    }
}

// ---------------- main GEMM kernel ----------------
#define NSTG     3
#define A_BYTES  16384                 // 128 rows x 128B (128 int8 ci)
#define STG      32768                 // A(16K) + B(16K)
#define GSMEM    (NSTG * STG)          // 98304 B -> 2 CTAs/SM
#define NCHUNK   18                    // 9 taps x 2 ci-chunks of 128

__global__ void __launch_bounds__(256, 2) bconv_gemm(float* __restrict__ out) {
    extern __shared__ char smem[];
    const uint32_t sbase = smem_u32(smem);
    const int tid  = threadIdx.x;
    const int warp = tid >> 5, lane = tid & 31;
    const int mw = warp >> 1;          // 0..3: M rows 32*mw..+31
    const int nw = warp & 1;           // 0..1: N cols 64*nw..+63
    const int bidx = blockIdx.x;
    const int co0  = (bidx & 1) * 128;
    const int m0   = (bidx >> 1) << 7;   // global M base (784*128 = 100352 exact)

    const int seg = tid & 7;   // 16B segment within 128B k-row
    const int rb  = tid >> 3;  // base row 0..31

    // ---- hoisted load addressing (loop-invariant per chunk) ----
    int aoff[4];
#pragma unroll
    for (int k = 0; k < 4; k++) {
        int m = m0 + rb + 32 * k;
        int ib  = m / HW;
        int rem = m - ib * HW;
        int h = rem / W_, w = rem - h * W_;
        aoff[k] = ((ib * HP + h) * WP + w) * CIN + seg * 16;
    }
    int boff[4];
#pragma unroll
    for (int k = 0; k < 4; k++) boff[k] = (co0 + rb + 32 * k) * CIN + seg * 16;
    const uint32_t dstb = rb * 128 + ((seg * 16) ^ ((rb & 7) << 4));

    const int rlo   = lane & 15;
    const int khalf = (lane >> 4) << 4;
    const int swz   = (rlo & 7) << 4;

    int d[2][8][4];
#pragma unroll
    for (int mi = 0; mi < 2; mi++)
#pragma unroll
        for (int ni = 0; ni < 8; ni++)
#pragma unroll
            for (int j = 0; j < 4; j++) d[mi][ni][j] = 0;

    auto load_chunk = [&](int chunk, int stage) {
        const int t  = chunk >> 1;                 // tap 0..8
        const int cc = (chunk & 1) << 7;           // ci base (0 or 128)
        const int kh = t / 3, kw = t - kh * 3;
        const int toffA = (kh * WP + kw) * CIN + cc;
        const int toffB = t * (COUT * CIN) + cc;
        const uint32_t stgA = sbase + stage * STG + dstb;
        const uint32_t stgB = stgA + A_BYTES;
#pragma unroll
        for (int k = 0; k < 4; k++)
            CP16(stgA + k * 4096, (const char*)g_xb + aoff[k] + toffA);
#pragma unroll
        for (int k = 0; k < 4; k++)
            CP16(stgB + k * 4096, (const char*)g_wb + boff[k] + toffB);
    };

    load_chunk(0, 0); CP_COMMIT();
    load_chunk(1, 1); CP_COMMIT();

    const int rowA0 = 32 * mw + rlo;
    const int rowB0 = 64 * nw + rlo;

    int stage = 2;                 // stage to fill next
    for (int i = 0; i < NCHUNK; i++) {
        CP_WAIT(1);
        __syncthreads();
        if (i + 2 < NCHUNK) load_chunk(i + 2, stage);
        CP_COMMIT();

        const int cur = (stage == 2) ? 0 : stage + 1;   // = i % 3
        stage = cur;
        const uint32_t stgA = sbase + cur * STG;
        const uint32_t stgB = stgA + A_BYTES;
#pragma unroll
        for (int ks = 0; ks < 4; ks++) {
            const int kb = ks * 32 + khalf;
            uint32_t a[2][4], bf[4][4];
            LDSM4(a[0], stgA + rowA0 * 128 + (kb ^ swz));
            LDSM4(a[1], stgA + (rowA0 + 16) * 128 + (kb ^ swz));
#pragma unroll
            for (int np = 0; np < 4; np++)
                LDSM4(bf[np], stgB + (rowB0 + 16 * np) * 128 + (kb ^ swz));
#pragma unroll
            for (int np = 0; np < 4; np++) {
                MMAI(d[0][2 * np],     a[0], bf[np][0], bf[np][2]);
                MMAI(d[0][2 * np + 1], a[0], bf[np][1], bf[np][3]);
                MMAI(d[1][2 * np],     a[1], bf[np][0], bf[np][2]);
                MMAI(d[1][2 * np + 1], a[1], bf[np][1], bf[np][3]);
            }
        }
    }

    CP_WAIT(0);
    __syncthreads();

    // ---------------- epilogue ----------------
    int*  buf    = (int*)smem;                     // 64 cl x 128 rows = 32KB
    int*  stable = (int*)(smem + 40960);           // 128-entry row -> out offset (co=0)
    if (tid < 128) {
        int m = m0 + tid;
        int ib  = m / HW;
        int rem = m - ib * HW;
        stable[tid] = ib * (COUT * HW) + rem;      // + co*HW gives final offset
    }
    const int q  = lane & 3;
    const int rr = lane >> 2;
#pragma unroll 1
    for (int hh = 0; hh < 2; hh++) {
        if (nw == hh) {
#pragma unroll
            for (int mi = 0; mi < 2; mi++)
#pragma unroll
                for (int ni = 0; ni < 8; ni++) {
                    int cl  = 8 * ni + 2 * q;
                    int row = 32 * mw + 16 * mi + rr;
                    buf[cl * 128 + row]           = d[mi][ni][0];
                    buf[(cl + 1) * 128 + row]     = d[mi][ni][1];
                    buf[cl * 128 + row + 8]       = d[mi][ni][2];
                    buf[(cl + 1) * 128 + row + 8] = d[mi][ni][3];
                }
        }
        __syncthreads();
#pragma unroll 4
        for (int it = 0; it < 32; it++) {
            int u  = tid + 256 * it;               // 0..8191
            int cl = u >> 7;
            int r  = u & 127;
            int co = co0 + hh * 64 + cl;
            out[stable[r] + co * HW] = (float)buf[cl * 128 + r] * __ldg(&g_sa[co]);
        }
        __syncthreads();
    }
}

// ---------------- launch ----------------
extern "C" void kernel_launch(void* const* d_in, const int* in_sizes, int n_in,
                              void* d_out, int out_size) {
    const float* x     = (const float*)d_in[0];  // [32,256,56,56]
    const float* wts   = (const float*)d_in[1];  // [4,256,256,3,3]
    const float* rv    = (const float*)d_in[2];  // [5]
    const float* alpha = (const float*)d_in[3];  // [256]
    float* out = (float*)d_out;

    cudaFuncSetAttribute(bconv_gemm, cudaFuncAttributeMaxDynamicSharedMemorySize, GSMEM);

    prep_all<<<COUT + 4 * H_ * B_, 256>>>(wts, rv, alpha, x);
    bconv_gemm<<<784 * 2, 256, GSMEM>>>(out);
}